// round 10
// baseline (speedup 1.0000x reference)
#include <cuda_runtime.h>
#include <cuda_bf16.h>
#include <math.h>

#define BATCH   32768
#define EPS     1e-5f

// ---------------- scratch (device globals; no cudaMalloc allowed) ----------
__device__ float g_h [ (size_t)BATCH * 300 ];
__device__ float g_m [ (size_t)BATCH * 400 ];
__device__ float g_ap[ (size_t)BATCH * 150 ];
__device__ float g_a [ (size_t)BATCH * 63  ];

#define STATS_TOTAL 860
__device__ float g_sum  [STATS_TOTAL];
__device__ float g_sq   [STATS_TOTAL];
__device__ float g_scale[STATS_TOTAL];
__device__ float g_shift[STATS_TOTAL];

__device__ __forceinline__ float* sel_buf(int s) {
    switch (s) {
        case 0: return g_h;
        case 1: return g_m;
        case 2: return g_ap;
        case 3: return g_a;
    }
    return nullptr;
}

__global__ void zero_stats_kernel() {
    int i = blockIdx.x * blockDim.x + threadIdx.x;
    if (i < STATS_TOTAL) { g_sum[i] = 0.f; g_sq[i] = 0.f; }
}

__global__ void finalize_stats_kernel(const float* __restrict__ g,
                                      const float* __restrict__ be,
                                      int off, int n, float invB) {
    int i = blockIdx.x * blockDim.x + threadIdx.x;
    if (i < n) {
        float mean = g_sum[off + i] * invB;
        float var  = g_sq [off + i] * invB - mean * mean;
        float s    = g[i] * rsqrtf(var + EPS);
        g_scale[off + i] = s;
        g_shift[off + i] = be[i] - mean * s;
    }
}

// ---------------- tf32 helpers ----------------------------------------------
__device__ __forceinline__ unsigned int f2tf32(float x) {
    unsigned int r;
    asm("cvt.rna.tf32.f32 %0, %1;" : "=r"(r) : "f"(x));
    return r;
}

__device__ __forceinline__ void mma_tf32(float c[4], const unsigned int a[4],
                                         unsigned int b0, unsigned int b1) {
    asm("mma.sync.aligned.m16n8k8.row.col.f32.tf32.tf32.f32 "
        "{%0,%1,%2,%3}, {%4,%5,%6,%7}, {%8,%9}, {%0,%1,%2,%3};"
        : "+f"(c[0]), "+f"(c[1]), "+f"(c[2]), "+f"(c[3])
        : "r"(a[0]), "r"(a[1]), "r"(a[2]), "r"(a[3]), "r"(b0), "r"(b1));
}

// ============================================================================
// Tensor-core GEMM via 3xTF32: BM=128, BN=64, BK=16, 256 threads (8 warps).
// Warp grid 4(m) x 2(n), warp tile 32x32, mma.m16n8k8.
// Smem: tf32 hi/lo bit patterns, padded strides (136/72) for conflict-free
// fragment loads (bank = 8*k + idx covers all 32 banks).
// ============================================================================
template<bool RELU, bool STATS, bool NORM>
__global__ void __launch_bounds__(256)
tgemm_kernel(const float* __restrict__ Aext, int Asel,
             const float* __restrict__ W,
             const float* __restrict__ bias,
             int normOff,
             float* __restrict__ Cext, int Csel, size_t cBudget,
             int statOff,
             int N, int K)
{
    const int BM = 128, BN = 64, BK = 16;
    const int AS = 136, WSd = 72;
    __shared__ unsigned int Ah[BK][AS], Al[BK][AS];
    __shared__ unsigned int Wh[BK][WSd], Wl[BK][WSd];
    __shared__ float sSum[BN], sSq[BN];

    const float* A = (Asel >= 0) ? sel_buf(Asel) : Aext;
    float*       C = (Csel >= 0) ? sel_buf(Csel) : Cext;

    const int m0   = blockIdx.y * BM;
    const int n0   = blockIdx.x * BN;
    const int tid  = threadIdx.x;
    const int wid  = tid >> 5;
    const int lane = tid & 31;
    const int g    = lane >> 2;      // groupID 0..7
    const int tg   = lane & 3;       // threadInGroup 0..3
    const int wm   = (wid >> 1) * 32;
    const int wn   = (wid & 1) * 32;

    // loaders' coords
    const int arow = tid >> 1;           // 0..127
    const int ak   = (tid & 1) * 8;      // 0 or 8
    const int wk   = tid >> 4;           // 0..15
    const int wn4  = (tid & 15) * 4;     // 0..60

    const float* Arow = A + (size_t)(m0 + arow) * K;

    if (tid < BN) { sSum[tid] = 0.f; sSq[tid] = 0.f; }

    float c[2][4][4];
    #pragma unroll
    for (int t = 0; t < 2; t++)
        #pragma unroll
        for (int u = 0; u < 4; u++)
            #pragma unroll
            for (int v = 0; v < 4; v++) c[t][u][v] = 0.f;

    for (int k0 = 0; k0 < K; k0 += BK) {
        // ---- load A slice: row arow, k = k0+ak .. +7 ------------------------
        #pragma unroll
        for (int q = 0; q < 8; q++) {
            int k = k0 + ak + q;
            float v = 0.f;
            if (k < K) {
                v = Arow[k];
                if (NORM) v = fmaf(v, g_scale[normOff + k], g_shift[normOff + k]);
            }
            unsigned int hi = f2tf32(v);
            float lo = v - __uint_as_float(hi);
            Ah[ak + q][arow] = hi;
            Al[ak + q][arow] = f2tf32(lo);
        }
        // ---- load W slice: row k0+wk, cols n0+wn4 .. +3 ---------------------
        {
            int k = k0 + wk;
            #pragma unroll
            for (int j = 0; j < 4; j++) {
                int n = n0 + wn4 + j;
                float v = (k < K && n < N) ? W[(size_t)k * N + n] : 0.f;
                unsigned int hi = f2tf32(v);
                float lo = v - __uint_as_float(hi);
                Wh[wk][wn4 + j] = hi;
                Wl[wk][wn4 + j] = f2tf32(lo);
            }
        }
        __syncthreads();

        // ---- compute: 2 k-chunks of 8 ---------------------------------------
        #pragma unroll
        for (int kc = 0; kc < BK; kc += 8) {
            unsigned int ah[2][4], al[2][4];
            #pragma unroll
            for (int t = 0; t < 2; t++) {
                int r0 = wm + t * 16 + g;
                ah[t][0] = Ah[kc + tg][r0];     ah[t][1] = Ah[kc + tg][r0 + 8];
                ah[t][2] = Ah[kc + tg + 4][r0]; ah[t][3] = Ah[kc + tg + 4][r0 + 8];
                al[t][0] = Al[kc + tg][r0];     al[t][1] = Al[kc + tg][r0 + 8];
                al[t][2] = Al[kc + tg + 4][r0]; al[t][3] = Al[kc + tg + 4][r0 + 8];
            }
            #pragma unroll
            for (int u = 0; u < 4; u++) {
                int cn = wn + u * 8 + g;
                unsigned int bh0 = Wh[kc + tg][cn],     bh1 = Wh[kc + tg + 4][cn];
                unsigned int bl0 = Wl[kc + tg][cn],     bl1 = Wl[kc + tg + 4][cn];
                #pragma unroll
                for (int t = 0; t < 2; t++) {
                    mma_tf32(c[t][u], ah[t], bh0, bh1);   // hi*hi
                    mma_tf32(c[t][u], al[t], bh0, bh1);   // lo*hi
                    mma_tf32(c[t][u], ah[t], bl0, bl1);   // hi*lo
                }
            }
        }
        __syncthreads();
    }

    // ---- epilogue: bias, relu, store, stats ---------------------------------
    float colS[8], colQ[8];
    #pragma unroll
    for (int j = 0; j < 8; j++) { colS[j] = 0.f; colQ[j] = 0.f; }

    #pragma unroll
    for (int t = 0; t < 2; t++) {
        const int r0 = m0 + wm + t * 16 + g;
        #pragma unroll
        for (int u = 0; u < 4; u++) {
            const int colb = n0 + wn + u * 8 + 2 * tg;
            const float bv0 = (colb < N)     ? bias[colb]     : 0.f;
            const float bv1 = (colb + 1 < N) ? bias[colb + 1] : 0.f;
            float x0 = c[t][u][0] + bv0, x1 = c[t][u][1] + bv1;
            float x2 = c[t][u][2] + bv0, x3 = c[t][u][3] + bv1;
            if (RELU) {
                x0 = fmaxf(x0, 0.f); x1 = fmaxf(x1, 0.f);
                x2 = fmaxf(x2, 0.f); x3 = fmaxf(x3, 0.f);
            }
            const size_t i0 = (size_t)r0 * N + colb;
            const size_t i1 = (size_t)(r0 + 8) * N + colb;
            if (colb + 1 < N) {
                if ((i0 + 2) * 4 <= cBudget) *(float2*)(C + i0) = make_float2(x0, x1);
                if ((i1 + 2) * 4 <= cBudget) *(float2*)(C + i1) = make_float2(x2, x3);
            } else if (colb < N) {
                if ((i0 + 1) * 4 <= cBudget) C[i0] = x0;
                if ((i1 + 1) * 4 <= cBudget) C[i1] = x2;
            }
            if (STATS) {
                const int j = u * 2;
                if (colb < N)     { colS[j]   += x0 + x2; colQ[j]   += x0*x0 + x2*x2; }
                if (colb + 1 < N) { colS[j+1] += x1 + x3; colQ[j+1] += x1*x1 + x3*x3; }
            }
        }
    }

    if (STATS) {
        #pragma unroll
        for (int u = 0; u < 4; u++)
            #pragma unroll
            for (int p = 0; p < 2; p++) {
                int ln = wn + u * 8 + 2 * tg + p;
                atomicAdd(&sSum[ln], colS[u * 2 + p]);
                atomicAdd(&sSq [ln], colQ[u * 2 + p]);
            }
        __syncthreads();
        if (tid < BN) {
            int n = n0 + tid;
            if (n < N) {
                atomicAdd(&g_sum[statOff + n], sSum[tid]);
                atomicAdd(&g_sq [statOff + n], sSq [tid]);
            }
        }
    }
}

// ---------------- packed fp32x2 primitives ----------------------------------
typedef unsigned long long u64;

__device__ __forceinline__ u64 pack_dup(float x) {
    u64 r;
    asm("mov.b64 %0, {%1, %1};" : "=l"(r) : "r"(__float_as_uint(x)));
    return r;
}
__device__ __forceinline__ void unpack2(u64 v, float& x, float& y) {
    unsigned int a, b;
    asm("mov.b64 {%0, %1}, %2;" : "=r"(a), "=r"(b) : "l"(v));
    x = __uint_as_float(a);
    y = __uint_as_float(b);
}
__device__ __forceinline__ void fma2(u64& d, u64 a, u64 b) {
    asm("fma.rn.f32x2 %0, %1, %2, %3;" : "=l"(d) : "l"(a), "l"(b), "l"(d));
}

// ---------------- tile loaders (global -> registers) ------------------------
template<bool NORM>
__device__ __forceinline__ void load_A_regs(const float* __restrict__ Arow,
                                            int k0, int K, int normOff,
                                            float av[16])
{
    if (k0 + 16 <= K) {
        const float4* p = (const float4*)(Arow + k0);
        float4 t0 = p[0], t1 = p[1], t2 = p[2], t3 = p[3];
        av[0]=t0.x; av[1]=t0.y; av[2]=t0.z; av[3]=t0.w;
        av[4]=t1.x; av[5]=t1.y; av[6]=t1.z; av[7]=t1.w;
        av[8]=t2.x; av[9]=t2.y; av[10]=t2.z; av[11]=t2.w;
        av[12]=t3.x; av[13]=t3.y; av[14]=t3.z; av[15]=t3.w;
        if (NORM) {
            #pragma unroll
            for (int q = 0; q < 16; q++)
                av[q] = fmaf(av[q], g_scale[normOff + k0 + q],
                                    g_shift[normOff + k0 + q]);
        }
    } else {
        #pragma unroll
        for (int q = 0; q < 16; q++) {
            int k = k0 + q;
            float v = 0.f;
            if (k < K) {
                v = Arow[k];
                if (NORM) v = fmaf(v, g_scale[normOff + k], g_shift[normOff + k]);
            }
            av[q] = v;
        }
    }
}

__device__ __forceinline__ void load_W_regs(const float* __restrict__ W,
                                            int k0, int wk, int n0, int wn,
                                            int N, int K, bool wVec,
                                            float4& w0, float4& w1)
{
    w0 = make_float4(0.f,0.f,0.f,0.f);
    w1 = w0;
    int k = k0 + wk;
    int n = n0 + wn;
    if (k < K) {
        const float* wr = W + (size_t)k * N;
        if (wVec && n + 8 <= N) {
            w0 = *(const float4*)(wr + n);
            w1 = *(const float4*)(wr + n + 4);
        } else {
            float t[8];
            #pragma unroll
            for (int j = 0; j < 8; j++)
                t[j] = (n + j < N) ? wr[n + j] : 0.f;
            w0 = make_float4(t[0],t[1],t[2],t[3]);
            w1 = make_float4(t[4],t[5],t[6],t[7]);
        }
    }
}

// ============================================================================
// FFMA2 GEMM (kept for small/odd layers)
// ============================================================================
template<bool RELU, bool STATS, bool NORM>
__global__ void __launch_bounds__(128)
fgemm_kernel(const float* __restrict__ Aext, int Asel,
             const float* __restrict__ W,
             const float* __restrict__ bias,
             int normOff,
             float* __restrict__ Cext, int Csel, size_t cBudget,
             int statOff,
             int N, int K)
{
    const int BM = 128, BN = 64, BK = 16;
    __shared__ __align__(16) float As[2][BK][BM];
    __shared__ __align__(16) float Ws[2][BK][BN];
    __shared__ float sSum[BN], sSq[BN];

    const float* A = (Asel >= 0) ? sel_buf(Asel) : Aext;
    float*       C = (Csel >= 0) ? sel_buf(Csel) : Cext;

    const int m0  = blockIdx.y * BM;
    const int n0  = blockIdx.x * BN;
    const int tid = threadIdx.x;
    const int mg  = tid >> 3;
    const int ng  = tid & 7;
    const int wk  = tid >> 3;
    const int wn  = (tid & 7) * 8;

    const float* Arow = A + (size_t)(m0 + tid) * K;
    const bool wVec = ((N & 3) == 0);

    u64 acc2[8][4];
    #pragma unroll
    for (int i = 0; i < 8; i++)
        #pragma unroll
        for (int p = 0; p < 4; p++) acc2[i][p] = 0ull;

    const int nTiles = (K + BK - 1) / BK;

    float av[16];
    float4 w0, w1;
    load_A_regs<NORM>(Arow, 0, K, normOff, av);
    load_W_regs(W, 0, wk, n0, wn, N, K, wVec, w0, w1);
    #pragma unroll
    for (int q = 0; q < 16; q++) As[0][q][tid] = av[q];
    *(float4*)&Ws[0][wk][wn]     = w0;
    *(float4*)&Ws[0][wk][wn + 4] = w1;
    __syncthreads();

    for (int t = 0; t < nTiles; t++) {
        const int buf = t & 1;
        const bool more = (t + 1 < nTiles);
        if (more) {
            load_A_regs<NORM>(Arow, (t + 1) * BK, K, normOff, av);
            load_W_regs(W, (t + 1) * BK, wk, n0, wn, N, K, wVec, w0, w1);
        }
        #pragma unroll
        for (int kk = 0; kk < BK; kk++) {
            float4 a0 = *(const float4*)&As[buf][kk][mg * 8];
            float4 a1 = *(const float4*)&As[buf][kk][mg * 8 + 4];
            ulonglong2 bq0 = *(const ulonglong2*)&Ws[buf][kk][ng * 4];
            ulonglong2 bq1 = *(const ulonglong2*)&Ws[buf][kk][32 + ng * 4];
            u64 bb[4] = { bq0.x, bq0.y, bq1.x, bq1.y };
            float ar[8] = {a0.x,a0.y,a0.z,a0.w,a1.x,a1.y,a1.z,a1.w};
            #pragma unroll
            for (int i = 0; i < 8; i++) {
                u64 ai = pack_dup(ar[i]);
                #pragma unroll
                for (int p = 0; p < 4; p++)
                    fma2(acc2[i][p], ai, bb[p]);
            }
        }
        if (more) {
            const int nb = buf ^ 1;
            #pragma unroll
            for (int q = 0; q < 16; q++) As[nb][q][tid] = av[q];
            *(float4*)&Ws[nb][wk][wn]     = w0;
            *(float4*)&Ws[nb][wk][wn + 4] = w1;
            __syncthreads();
        }
    }

    float colSum[8], colSq[8];
    #pragma unroll
    for (int j = 0; j < 8; j++) { colSum[j] = 0.f; colSq[j] = 0.f; }

    const int cA = n0 + ng * 4;
    const int cB = n0 + 32 + ng * 4;
    float bvA[4], bvB[4];
    #pragma unroll
    for (int j = 0; j < 4; j++) {
        bvA[j] = (cA + j < N) ? bias[cA + j] : 0.f;
        bvB[j] = (cB + j < N) ? bias[cB + j] : 0.f;
    }

    #pragma unroll
    for (int i = 0; i < 8; i++) {
        const int m = m0 + mg * 8 + i;
        float vA[4], vB[4];
        unpack2(acc2[i][0], vA[0], vA[1]);
        unpack2(acc2[i][1], vA[2], vA[3]);
        unpack2(acc2[i][2], vB[0], vB[1]);
        unpack2(acc2[i][3], vB[2], vB[3]);
        #pragma unroll
        for (int j = 0; j < 4; j++) {
            float cc = vA[j] + bvA[j];
            if (RELU) cc = fmaxf(cc, 0.f);
            vA[j] = cc;
            if (STATS && cA + j < N) { colSum[j] += cc; colSq[j] += cc * cc; }
            cc = vB[j] + bvB[j];
            if (RELU) cc = fmaxf(cc, 0.f);
            vB[j] = cc;
            if (STATS && cB + j < N) { colSum[4 + j] += cc; colSq[4 + j] += cc * cc; }
        }
        const size_t rowBase = (size_t)m * N;
        if (wVec && cA + 4 <= N && (rowBase + cA + 4) * 4 <= cBudget) {
            *(float4*)(C + rowBase + cA) = make_float4(vA[0],vA[1],vA[2],vA[3]);
        } else {
            #pragma unroll
            for (int j = 0; j < 4; j++)
                if (cA + j < N && (rowBase + cA + j + 1) * 4 <= cBudget)
                    C[rowBase + cA + j] = vA[j];
        }
        if (wVec && cB + 4 <= N && (rowBase + cB + 4) * 4 <= cBudget) {
            *(float4*)(C + rowBase + cB) = make_float4(vB[0],vB[1],vB[2],vB[3]);
        } else {
            #pragma unroll
            for (int j = 0; j < 4; j++)
                if (cB + j < N && (rowBase + cB + j + 1) * 4 <= cBudget)
                    C[rowBase + cB + j] = vB[j];
        }
    }

    if (STATS) {
        if (tid < BN) { sSum[tid] = 0.f; sSq[tid] = 0.f; }
        __syncthreads();
        #pragma unroll
        for (int j = 0; j < 4; j++) {
            atomicAdd(&sSum[ng * 4 + j],      colSum[j]);
            atomicAdd(&sSq [ng * 4 + j],      colSq [j]);
            atomicAdd(&sSum[32 + ng * 4 + j], colSum[4 + j]);
            atomicAdd(&sSq [32 + ng * 4 + j], colSq [4 + j]);
        }
        __syncthreads();
        if (tid < BN) {
            int n = n0 + tid;
            if (n < N) {
                atomicAdd(&g_sum[statOff + n], sSum[tid]);
                atomicAdd(&g_sq [statOff + n], sSq [tid]);
            }
        }
    }
}

// ---------------- small scalar GEMM (N=63 final projection) ----------------
template<bool RELU, bool STATS, bool NORM>
__global__ void __launch_bounds__(256, 4)
sgemm_kernel(const float* __restrict__ Aext, int Asel,
             const float* __restrict__ W,
             const float* __restrict__ bias,
             int normOff,
             float* __restrict__ Cext, int Csel,
             int statOff,
             int N, int K)
{
    const int BM = 128, BN = 64, BK = 8, TM = 8, TN = 4;
    __shared__ float As[BK][BM];
    __shared__ float Ws[BK][BN];

    const float* A = (Asel >= 0) ? sel_buf(Asel) : Aext;
    float*       C = (Csel >= 0) ? sel_buf(Csel) : Cext;

    const int m0  = blockIdx.y * BM;
    const int n0  = blockIdx.x * BN;
    const int tid = threadIdx.x;
    const int tx  = tid & 15;
    const int ty  = tid >> 4;

    float acc[TM][TN];
    #pragma unroll
    for (int i = 0; i < TM; i++)
        #pragma unroll
        for (int j = 0; j < TN; j++) acc[i][j] = 0.f;

    for (int k0 = 0; k0 < K; k0 += BK) {
        #pragma unroll
        for (int i = 0; i < 4; i++) {
            int idx = tid + i * 256;
            int mm  = idx >> 3;
            int kk  = idx & 7;
            int k   = k0 + kk;
            float v = 0.f;
            if (k < K) {
                v = A[(size_t)(m0 + mm) * K + k];
                if (NORM) v = fmaf(v, g_scale[normOff + k], g_shift[normOff + k]);
            }
            As[kk][mm] = v;
        }
        #pragma unroll
        for (int i = 0; i < 2; i++) {
            int idx = tid + i * 256;
            int kk  = idx >> 6;
            int nn  = idx & 63;
            int k   = k0 + kk, n = n0 + nn;
            Ws[kk][nn] = (k < K && n < N) ? W[(size_t)k * N + n] : 0.f;
        }
        __syncthreads();
        #pragma unroll
        for (int kk = 0; kk < BK; kk++) {
            float ar[TM], br[TN];
            #pragma unroll
            for (int i = 0; i < TM; i++) ar[i] = As[kk][ty * TM + i];
            #pragma unroll
            for (int j = 0; j < TN; j++) br[j] = Ws[kk][tx * TN + j];
            #pragma unroll
            for (int i = 0; i < TM; i++)
                #pragma unroll
                for (int j = 0; j < TN; j++)
                    acc[i][j] = fmaf(ar[i], br[j], acc[i][j]);
        }
        __syncthreads();
    }

    #pragma unroll
    for (int j = 0; j < TN; j++) {
        int n = n0 + tx * TN + j;
        if (n < N) {
            float bv = bias[n];
            #pragma unroll
            for (int i = 0; i < TM; i++) {
                float c = acc[i][j] + bv;
                if (RELU) c = fmaxf(c, 0.f);
                C[(size_t)(m0 + ty * TM + i) * N + n] = c;
            }
        }
    }
}

// ---------------- Toeplitz epilogue (REAL parts only, f32 output) -----------
__global__ void __launch_bounds__(256)
toeplitz_real_kernel(float* __restrict__ out,
                     size_t offB, size_t offC, size_t budgetElems)
{
    __shared__ float sre[8][32];
    const int warp = threadIdx.x >> 5;
    const int lane = threadIdx.x & 31;
    const int row  = blockIdx.x * 8 + warp;

    const float* ar = g_a + (size_t)row * 63;
    float v0 = ar[lane];
    float a0 = fminf(expf(__shfl_sync(0xffffffffu, v0, 0)), 500.f);

    float re = (lane == 0) ? a0 : (0.022f * a0 * tanhf(v0));
    sre[warp][lane] = re;
    __syncwarp();

    const size_t rbase = (size_t)row * 1024 + lane;
    #pragma unroll
    for (int i = 0; i < 32; i++) {
        int d = i - lane;
        float b = (d >= 0) ? sre[warp][d]      : 0.f;
        float c = (d >= 1) ? sre[warp][32 - d] : 0.f;
        size_t ib = offB + rbase + (size_t)i * 32;
        size_t ic = offC + rbase + (size_t)i * 32;
        if (ib < budgetElems) out[ib] = b;
        if (ic < budgetElems) out[ic] = c;
    }
}

// ---------------- launch -----------------------------------------------------
extern "C" void kernel_launch(void* const* d_in, const int* in_sizes, int n_in,
                              void* d_out, int out_size)
{
    if (n_in < 17) return;

    const float* z   = (const float*)d_in[0];
    const float* W1  = (const float*)d_in[1];
    const float* b1  = (const float*)d_in[2];
    const float* g1  = (const float*)d_in[3];
    const float* be1 = (const float*)d_in[4];
    const float* W2  = (const float*)d_in[5];
    const float* b2  = (const float*)d_in[6];
    const float* g2  = (const float*)d_in[7];
    const float* be2 = (const float*)d_in[8];
    const float* W3  = (const float*)d_in[9];
    const float* b3  = (const float*)d_in[10];
    const float* Wa1 = (const float*)d_in[11];
    const float* ba1 = (const float*)d_in[12];
    const float* ga  = (const float*)d_in[13];
    const float* bea = (const float*)d_in[14];
    const float* Wa2 = (const float*)d_in[15];
    const float* ba2 = (const float*)d_in[16];

    long long Braw = (long long)in_sizes[0] / 24;
    if (Braw > BATCH) Braw = BATCH;
    Braw -= (Braw % 128);
    if (Braw <= 0) return;
    const int B = (int)Braw;
    const long long LB = (long long)B;

    float* out = (float*)d_out;
    const float invB = 1.0f / (float)B;
    const size_t budgetBytes = (size_t)out_size * 4;
    const size_t budgetElems = (size_t)out_size;
    const size_t BIG = (size_t)-1;
    const int mB = B / 128;

    // 0. zero stat accumulators
    zero_stats_kernel<<<4, 256>>>();

    // 1. h = relu(z @ W1 + b1) -> g_h, stats @0        (K=24, N=300) [FFMA2]
    fgemm_kernel<true, true, false><<<dim3(5, mB), 128>>>(
        z, -1, W1, b1, 0, nullptr, 0, BIG, 0, 300, 24);

    // 2. finalize BN1
    finalize_stats_kernel<<<2, 256>>>(g1, be1, 0, 300, invB);

    // 3. m = relu(BN(h) @ W2 + b2) -> g_m, stats @300  (K=300, N=400) [tensor]
    tgemm_kernel<true, true, true><<<dim3(7, mB), 256>>>(
        nullptr, 0, W2, b2, 0, nullptr, 1, BIG, 300, 400, 300);

    // 4. ap = relu(BN(h) @ Wa1 + ba1) -> g_ap, stats @700 (K=300, N=150) [FFMA2]
    fgemm_kernel<true, true, true><<<dim3(3, mB), 128>>>(
        nullptr, 0, Wa1, ba1, 0, nullptr, 2, BIG, 700, 150, 300);

    // 5. finalize BN2, BNa
    finalize_stats_kernel<<<2, 256>>>(g2, be2, 300, 400, invB);
    finalize_stats_kernel<<<1, 256>>>(ga, bea, 700, 150, invB);

    // 6. mu_out = BN(m) @ W3 + b3 -> out[0..B*1024)   (K=400, N=1024) [tensor]
    tgemm_kernel<false, false, true><<<dim3(16, mB), 256>>>(
        nullptr, 1, W3, b3, 300, out, -1, budgetBytes, 0, 1024, 400);

    // 7. a = BN(ap) @ Wa2 + ba2 -> g_a   (K=150, N=63) [scalar]
    sgemm_kernel<false, false, true><<<dim3(1, mB), 256>>>(
        nullptr, 2, Wa2, ba2, 700, nullptr, 3, 0, 63, 150);

    // 8. Toeplitz real parts
    toeplitz_real_kernel<<<B / 8, 256>>>(out, (size_t)LB * 1024,
                                         (size_t)LB * 2048, budgetElems);
}